// round 14
// baseline (speedup 1.0000x reference)
#include <cuda_runtime.h>
#include <cuda_bf16.h>
#include <cstdint>

#define NB 4
#define LL 8192
#define SSZ 8192
#define HH 8
#define DD 64
#define NH (NB * HH)
#define CHA 32           // s-chunks per (n,h); 256 s per chunk
#define PART_STRIDE 4160 // 4096 kv + 64 ksum
#define EPS 1e-6f
#define BR 72            // B rows: 64 kv^T + 1 ksum + 7 zero
#define BSTR 144         // bf16 row stride bytes

typedef unsigned long long u64;
typedef unsigned int u32;

__device__ float g_part[NH * CHA * PART_STRIDE];
__device__ __nv_bfloat16 g_kvbf_hi[NH * BR * DD];
__device__ __nv_bfloat16 g_kvbf_lo[NH * BR * DD];

__device__ __forceinline__ float fmap(float x) {
    return x > 0.f ? x + 1.f : __expf(x);
}

__device__ __forceinline__ u32 smem_u32(const void* p) {
    u32 a;
    asm("{ .reg .u64 t; cvta.to.shared.u64 t, %1; cvt.u32.u64 %0, t; }"
        : "=r"(a) : "l"(p));
    return a;
}

__device__ __forceinline__ void cpasync16(u32 saddr, const void* gptr) {
    asm volatile("cp.async.cg.shared.global [%0], [%1], 16;"
                 :: "r"(saddr), "l"(gptr));
}
#define CP_COMMIT() asm volatile("cp.async.commit_group;" ::: "memory")
#define CP_WAIT1()  asm volatile("cp.async.wait_group 1;" ::: "memory")
#define CP_WAIT0()  asm volatile("cp.async.wait_group 0;" ::: "memory")

__device__ __forceinline__ void ldsm4(u32* r, u32 addr) {
    asm volatile("ldmatrix.sync.aligned.m8n8.x4.shared.b16 {%0,%1,%2,%3}, [%4];"
                 : "=r"(r[0]), "=r"(r[1]), "=r"(r[2]), "=r"(r[3]) : "r"(addr));
}
__device__ __forceinline__ void ldsm4t(u32* r, u32 addr) {
    asm volatile("ldmatrix.sync.aligned.m8n8.x4.trans.shared.b16 {%0,%1,%2,%3}, [%4];"
                 : "=r"(r[0]), "=r"(r[1]), "=r"(r[2]), "=r"(r[3]) : "r"(addr));
}
__device__ __forceinline__ void ldsm2(u32* r, u32 addr) {
    asm volatile("ldmatrix.sync.aligned.m8n8.x2.shared.b16 {%0,%1}, [%2];"
                 : "=r"(r[0]), "=r"(r[1]) : "r"(addr));
}
__device__ __forceinline__ void ldsm2t(u32* r, u32 addr) {
    asm volatile("ldmatrix.sync.aligned.m8n8.x2.trans.shared.b16 {%0,%1}, [%2];"
                 : "=r"(r[0]), "=r"(r[1]) : "r"(addr));
}

__device__ __forceinline__ void mma_bf16(float* c, const u32* a, u32 b0, u32 b1) {
    asm volatile(
        "mma.sync.aligned.m16n8k16.row.col.f32.bf16.bf16.f32 "
        "{%0,%1,%2,%3}, {%4,%5,%6,%7}, {%8,%9}, {%0,%1,%2,%3};"
        : "+f"(c[0]), "+f"(c[1]), "+f"(c[2]), "+f"(c[3])
        : "r"(a[0]), "r"(a[1]), "r"(a[2]), "r"(a[3]), "r"(b0), "r"(b1));
}

__device__ __forceinline__ unsigned short bfbits(float x) {
    __nv_bfloat16 b = __float2bfloat16_rn(x);
    return *(unsigned short*)&b;
}

__device__ __forceinline__ void split2(float f0, float f1, u32& hi, u32& lo) {
    unsigned short h0 = bfbits(f0), h1 = bfbits(f1);
    __nv_bfloat16 hv0 = *(__nv_bfloat16*)&h0, hv1 = *(__nv_bfloat16*)&h1;
    unsigned short l0 = bfbits(f0 - __bfloat162float(hv0));
    unsigned short l1 = bfbits(f1 - __bfloat162float(hv1));
    hi = (u32)h0 | ((u32)h1 << 16);
    lo = (u32)l0 | ((u32)l1 << 16);
}

// ================= Kernel A: kv partial, 16-row slab cp.async pipeline =================
// smem: 2x4KB f32 slabs per tensor + bf16 tiles => 34816 B => 6 CTAs/SM
#define KV_KF32 0                       // 2 x 4096
#define KV_VF32 8192                    // 2 x 4096
#define KV_KHI  16384                   // 32*144 each
#define KV_KLO  (16384 + 4608)
#define KV_VHI  (16384 + 9216)
#define KV_VLO  (16384 + 13824)
#define KV_SMEM_BYTES (16384 + 18432)   // 34816

__global__ __launch_bounds__(128, 6) void kv_mma_kernel(
    const float* __restrict__ kin, const float* __restrict__ vin,
    const float* __restrict__ kv_mask)
{
    extern __shared__ char smem[];
    const u32 sb = smem_u32(smem);
    const u32 sb_khi = sb + KV_KHI, sb_klo = sb + KV_KLO;
    const u32 sb_vhi = sb + KV_VHI, sb_vlo = sb + KV_VLO;

    const int nh = blockIdx.x;
    const int n = nh >> 3, h = nh & 7;
    const int s0 = blockIdx.y * 256;
    const int t = threadIdx.x;
    const int lane = t & 31, w = t >> 5;

    // ones column (v cols 64-71): col64=1.0
    if (t < 32) {
        *(uint4*)(smem + KV_VHI + t * BSTR + 128) = make_uint4(0x3F80u, 0u, 0u, 0u);
        *(uint4*)(smem + KV_VLO + t * BSTR + 128) = make_uint4(0u, 0u, 0u, 0u);
    }

    const size_t gbase = (((size_t)n * SSZ + s0) * HH + h) * DD;

    // prologue: slabs 0,1 (one commit-group each)
    #pragma unroll
    for (int s = 0; s < 2; s++) {
        #pragma unroll
        for (int j = 0; j < 2; j++) {
            int c = t + j * 128;
            int r = c >> 4, c16 = c & 15;
            size_t g = gbase + (size_t)(s * 16 + r) * (HH * DD) + c16 * 4;
            cpasync16(sb + KV_KF32 + s * 4096 + c * 16, kin + g);
            cpasync16(sb + KV_VF32 + s * 4096 + c * 16, vin + g);
        }
        CP_COMMIT();
    }

    float acc[9][4] = {};

    #pragma unroll 1
    for (int s = 0; s < 16; s++) {
        const int buf = s & 1;
        if (s < 15) { CP_WAIT1(); } else { CP_WAIT0(); }

        // convert own chunks (writer==reader, no barrier)
        #pragma unroll
        for (int e = 0; e < 2; e++) {
            int idx = t + e * 128;
            int r = idx >> 4, c4 = (idx & 15) * 4;
            float m = kv_mask[n * SSZ + s0 + s * 16 + r];
            float4 kq = *(const float4*)(smem + KV_KF32 + buf * 4096 + idx * 16);
            float4 vq = *(const float4*)(smem + KV_VF32 + buf * 4096 + idx * 16);
            u32 kh0, kl0, kh1, kl1, vh0, vl0, vh1, vl1;
            split2(fmap(kq.x) * m, fmap(kq.y) * m, kh0, kl0);
            split2(fmap(kq.z) * m, fmap(kq.w) * m, kh1, kl1);
            split2(vq.x * m, vq.y * m, vh0, vl0);
            split2(vq.z * m, vq.w * m, vh1, vl1);
            u32 off = (u32)(buf * 16 + r) * BSTR + c4 * 2;
            *(u32*)(smem + KV_KHI + off) = kh0; *(u32*)(smem + KV_KHI + off + 4) = kh1;
            *(u32*)(smem + KV_KLO + off) = kl0; *(u32*)(smem + KV_KLO + off + 4) = kl1;
            *(u32*)(smem + KV_VHI + off) = vh0; *(u32*)(smem + KV_VHI + off + 4) = vh1;
            *(u32*)(smem + KV_VLO + off) = vl0; *(u32*)(smem + KV_VLO + off + 4) = vl1;
        }

        // issue slab s+2 into the buffer just freed
        if (s + 2 < 16) {
            #pragma unroll
            for (int j = 0; j < 2; j++) {
                int c = t + j * 128;
                int r = c >> 4, c16 = c & 15;
                size_t g = gbase + (size_t)((s + 2) * 16 + r) * (HH * DD) + c16 * 4;
                cpasync16(sb + KV_KF32 + buf * 4096 + c * 16, kin + g);
                cpasync16(sb + KV_VF32 + buf * 4096 + c * 16, vin + g);
            }
            CP_COMMIT();
        }

        if (s & 1) {
            __syncthreads();
            // MMA over the full 32-row bf16 tile (verified mapping)
            #pragma unroll
            for (int kk = 0; kk < 2; kk++) {
                u32 arow = (u32)((lane & 7) + ((lane >> 4) & 1) * 8 + kk * 16);
                u32 acol = (u32)(w * 16 + ((lane >> 3) & 1) * 8);
                u32 aoff = arow * BSTR + acol * 2;
                u32 ahi[4], alo[4];
                ldsm4t(ahi, sb_khi + aoff);
                ldsm4t(alo, sb_klo + aoff);

                u32 brow = (u32)((lane & 7) + ((lane >> 3) & 1) * 8 + kk * 16);
                #pragma unroll
                for (int p = 0; p < 4; p++) {
                    u32 boff = brow * BSTR + (u32)(p * 16 + ((lane >> 4) & 1) * 8) * 2;
                    u32 bh[4], bl[4];
                    ldsm4t(bh, sb_vhi + boff);
                    ldsm4t(bl, sb_vlo + boff);
                    mma_bf16(acc[2 * p],     ahi, bh[0], bh[1]);
                    mma_bf16(acc[2 * p],     ahi, bl[0], bl[1]);
                    mma_bf16(acc[2 * p],     alo, bh[0], bh[1]);
                    mma_bf16(acc[2 * p + 1], ahi, bh[2], bh[3]);
                    mma_bf16(acc[2 * p + 1], ahi, bl[2], bl[3]);
                    mma_bf16(acc[2 * p + 1], alo, bh[2], bh[3]);
                }
                {
                    u32 b2off = brow * BSTR + 64 * 2;
                    u32 bh[2], bl[2];
                    ldsm2t(bh, sb_vhi + b2off);
                    ldsm2t(bl, sb_vlo + b2off);
                    mma_bf16(acc[8], ahi, bh[0], bh[1]);
                    mma_bf16(acc[8], ahi, bl[0], bl[1]);
                    mma_bf16(acc[8], alo, bh[0], bh[1]);
                }
            }
            __syncthreads();
        }
    }

    float* part = &g_part[(nh * CHA + blockIdx.y) * PART_STRIDE];
    const int r0 = w * 16 + (lane >> 2);
    const int col = 2 * (lane & 3);
    #pragma unroll
    for (int nt = 0; nt < 8; nt++) {
        *(float2*)&part[r0 * 64 + nt * 8 + col] = make_float2(acc[nt][0], acc[nt][1]);
        *(float2*)&part[(r0 + 8) * 64 + nt * 8 + col] = make_float2(acc[nt][2], acc[nt][3]);
    }
    if ((lane & 3) == 0) {
        part[4096 + r0] = acc[8][0];
        part[4096 + r0 + 8] = acc[8][2];
    }
}

// ================= Reduce: fp32 sum -> transposed bf16 hi/lo =================
__global__ __launch_bounds__(256) void kv_reduce_kernel() {
    int idx = blockIdx.x * 256 + threadIdx.x;
    int nh = idx / PART_STRIDE;
    int el = idx - nh * PART_STRIDE;
    float s = 0.f;
    #pragma unroll 8
    for (int ch = 0; ch < CHA; ch++)
        s += g_part[(nh * CHA + ch) * PART_STRIDE + el];

    __nv_bfloat16 hi = __float2bfloat16_rn(s);
    __nv_bfloat16 lo = __float2bfloat16_rn(s - __bfloat162float(hi));

    int dst;
    if (el < 4096) {
        int d = el >> 6, v = el & 63;
        dst = nh * (BR * DD) + v * 64 + d;
    } else {
        int d = el - 4096;
        dst = nh * (BR * DD) + 64 * 64 + d;
    }
    g_kvbf_hi[dst] = hi;
    g_kvbf_lo[dst] = lo;
}

// ================= Kernel B: HMMA out, q slab pipeline =================
// smem: 2x4KB q slabs + A hi/lo + B hi/lo = 65792 B => 3 CTAs/SM (regs capped)
#define O_QF32 0                        // 2 x 4096
#define O_AHI  8192                     // 128*144 = 18432
#define O_ALO  (8192 + 18432)
#define O_BHI  (8192 + 36864)           // 72*144 = 10368
#define O_BLO  (8192 + 36864 + 10368)
#define OUT_SMEM_BYTES (8192 + 36864 + 20736)   // 65792

__global__ __launch_bounds__(256, 3) void out_mma_kernel(
    const float* __restrict__ qin, const float* __restrict__ q_mask,
    float* __restrict__ out)
{
    extern __shared__ char smem[];
    const u32 sb = smem_u32(smem);

    const int nh = blockIdx.x;
    const int n = nh >> 3, h = nh & 7;
    const int l0 = blockIdx.y * 128;
    const int t = threadIdx.x;
    const int lane = t & 31, w = t >> 5;

    const size_t gqbase = (((size_t)n * LL + l0) * HH + h) * DD;

    // prologue: q slabs 0,1 in flight first
    #pragma unroll
    for (int s = 0; s < 2; s++) {
        int r = t >> 4, c16 = t & 15;
        size_t g = gqbase + (size_t)(s * 16 + r) * (HH * DD) + c16 * 4;
        cpasync16(sb + O_QF32 + s * 4096 + t * 16, qin + g);
        CP_COMMIT();
    }

    // stage B while q slabs load (72 rows x 64 bf16, hi/lo)
    {
        const u32* ghi = (const u32*)&g_kvbf_hi[nh * (BR * DD)];
        const u32* glo = (const u32*)&g_kvbf_lo[nh * (BR * DD)];
        #pragma unroll
        for (int e = 0; e < 9; e++) {
            int idx = t + e * 256;
            int row = idx >> 5, c = idx & 31;
            *(u32*)(smem + O_BHI + row * BSTR + c * 4) = ghi[idx];
            *(u32*)(smem + O_BLO + row * BSTR + c * 4) = glo[idx];
        }
    }

    // q slab pipeline: 8 slabs of 16 rows; 1 chunk per thread per slab
    #pragma unroll 1
    for (int s = 0; s < 8; s++) {
        const int buf = s & 1;
        if (s < 7) { CP_WAIT1(); } else { CP_WAIT0(); }

        {
            int r = t >> 4, c4 = (t & 15) * 4;
            int l = s * 16 + r;
            float m = q_mask[n * LL + l0 + l];
            float4 x = *(const float4*)(smem + O_QF32 + buf * 4096 + t * 16);
            u32 h0, lo0, h1, lo1;
            split2(fmap(x.x) * m, fmap(x.y) * m, h0, lo0);
            split2(fmap(x.z) * m, fmap(x.w) * m, h1, lo1);
            u32 off = (u32)l * BSTR + c4 * 2;
            *(u32*)(smem + O_AHI + off)     = h0;
            *(u32*)(smem + O_AHI + off + 4) = h1;
            *(u32*)(smem + O_ALO + off)     = lo0;
            *(u32*)(smem + O_ALO + off + 4) = lo1;
        }

        if (s + 2 < 8) {
            int r = t >> 4, c16 = t & 15;
            size_t g = gqbase + (size_t)((s + 2) * 16 + r) * (HH * DD) + c16 * 4;
            cpasync16(sb + O_QF32 + buf * 4096 + t * 16, qin + g);
            CP_COMMIT();
        }
    }
    __syncthreads();

    // MMA + epilogue (verified round-10 body)
    const int mbase = w * 16;
    float acc[9][4] = {};

    const u32 a_off = (u32)(mbase + (lane & 15)) * BSTR + (u32)(lane >> 4) * 16;
    const int bi = lane & 7, bg = lane >> 3;
    const u32 b4_off = (u32)(bi + ((bg & 2) << 2)) * BSTR + (u32)(bg & 1) * 16;
    const u32 b2_off = (u32)(64 + bi) * BSTR + (u32)(bg & 1) * 16;

    #pragma unroll
    for (int kk = 0; kk < 4; kk++) {
        const u32 koff = kk * 32;
        u32 ahi[4], alo[4];
        ldsm4(ahi, sb + O_AHI + a_off + koff);
        ldsm4(alo, sb + O_ALO + a_off + koff);

        #pragma unroll
        for (int p = 0; p < 4; p++) {
            u32 bh[4], bl[4];
            u32 ba = (u32)(p * 16) * BSTR + b4_off + koff;
            ldsm4(bh, sb + O_BHI + ba);
            ldsm4(bl, sb + O_BLO + ba);
            mma_bf16(acc[2 * p],     ahi, bh[0], bh[1]);
            mma_bf16(acc[2 * p],     ahi, bl[0], bl[1]);
            mma_bf16(acc[2 * p],     alo, bh[0], bh[1]);
            mma_bf16(acc[2 * p + 1], ahi, bh[2], bh[3]);
            mma_bf16(acc[2 * p + 1], ahi, bl[2], bl[3]);
            mma_bf16(acc[2 * p + 1], alo, bh[2], bh[3]);
        }
        {
            u32 bh[2], bl[2];
            ldsm2(bh, sb + O_BHI + b2_off + koff);
            ldsm2(bl, sb + O_BLO + b2_off + koff);
            mma_bf16(acc[8], ahi, bh[0], bh[1]);
            mma_bf16(acc[8], ahi, bl[0], bl[1]);
            mma_bf16(acc[8], alo, bh[0], bh[1]);
        }
    }

    float n0 = __shfl_sync(0xffffffffu, acc[8][0], lane & ~3);
    float n1 = __shfl_sync(0xffffffffu, acc[8][2], lane & ~3);
    float dv0 = 1.f / (n0 + EPS);
    float dv1 = 1.f / (n1 + EPS);

    const int r0 = l0 + mbase + (lane >> 2);
    const int col = 2 * (lane & 3);
    size_t g0 = (((size_t)(n * LL + r0)) * HH + h) * DD;
    size_t g1 = g0 + (size_t)8 * HH * DD;

    #pragma unroll
    for (int nt = 0; nt < 8; nt++) {
        *(float2*)&out[g0 + nt * 8 + col] =
            make_float2(acc[nt][0] * dv0, acc[nt][1] * dv0);
        *(float2*)&out[g1 + nt * 8 + col] =
            make_float2(acc[nt][2] * dv1, acc[nt][3] * dv1);
    }
}

extern "C" void kernel_launch(void* const* d_in, const int* in_sizes, int n_in,
                              void* d_out, int out_size)
{
    const float* q   = (const float*)d_in[0];
    const float* k   = (const float*)d_in[1];
    const float* v   = (const float*)d_in[2];
    const float* qm  = (const float*)d_in[3];
    const float* kvm = (const float*)d_in[4];
    float* out = (float*)d_out;

    static bool attr_done = false;
    if (!attr_done) {
        cudaFuncSetAttribute(kv_mma_kernel,
                             cudaFuncAttributeMaxDynamicSharedMemorySize,
                             KV_SMEM_BYTES);
        cudaFuncSetAttribute(out_mma_kernel,
                             cudaFuncAttributeMaxDynamicSharedMemorySize,
                             OUT_SMEM_BYTES);
        attr_done = true;
    }

    kv_mma_kernel<<<dim3(NH, CHA), 128, KV_SMEM_BYTES>>>(k, v, kvm);
    kv_reduce_kernel<<<(NH * PART_STRIDE) / 256, 256>>>();
    out_mma_kernel<<<dim3(NH, 64), 256, OUT_SMEM_BYTES>>>(q, qm, out);
}

// round 15
// speedup vs baseline: 1.0780x; 1.0780x over previous
#include <cuda_runtime.h>
#include <cuda_bf16.h>
#include <cstdint>

#define NB 4
#define LL 8192
#define SSZ 8192
#define HH 8
#define DD 64
#define NH (NB * HH)
#define CHA 32           // s-chunks per (n,h); 256 s per chunk
#define PART_STRIDE 4160 // 4096 kv + 64 ksum
#define EPS 1e-6f
#define BR 72            // B rows: 64 kv^T + 1 ksum + 7 zero
#define BSTR 144         // bf16 row stride bytes

typedef unsigned long long u64;
typedef unsigned int u32;

__device__ float g_part[NH * CHA * PART_STRIDE];
__device__ __nv_bfloat16 g_kvbf_hi[NH * BR * DD];
__device__ __nv_bfloat16 g_kvbf_lo[NH * BR * DD];

__device__ __forceinline__ float fmap(float x) {
    return x > 0.f ? x + 1.f : __expf(x);
}

__device__ __forceinline__ u32 smem_u32(const void* p) {
    u32 a;
    asm("{ .reg .u64 t; cvta.to.shared.u64 t, %1; cvt.u32.u64 %0, t; }"
        : "=r"(a) : "l"(p));
    return a;
}

__device__ __forceinline__ void cpasync16(u32 saddr, const void* gptr) {
    asm volatile("cp.async.cg.shared.global [%0], [%1], 16;"
                 :: "r"(saddr), "l"(gptr));
}
#define CP_COMMIT() asm volatile("cp.async.commit_group;" ::: "memory")
#define CP_WAIT1()  asm volatile("cp.async.wait_group 1;" ::: "memory")
#define CP_WAIT0()  asm volatile("cp.async.wait_group 0;" ::: "memory")

__device__ __forceinline__ void ldsm4(u32* r, u32 addr) {
    asm volatile("ldmatrix.sync.aligned.m8n8.x4.shared.b16 {%0,%1,%2,%3}, [%4];"
                 : "=r"(r[0]), "=r"(r[1]), "=r"(r[2]), "=r"(r[3]) : "r"(addr));
}
__device__ __forceinline__ void ldsm4t(u32* r, u32 addr) {
    asm volatile("ldmatrix.sync.aligned.m8n8.x4.trans.shared.b16 {%0,%1,%2,%3}, [%4];"
                 : "=r"(r[0]), "=r"(r[1]), "=r"(r[2]), "=r"(r[3]) : "r"(addr));
}
__device__ __forceinline__ void ldsm2(u32* r, u32 addr) {
    asm volatile("ldmatrix.sync.aligned.m8n8.x2.shared.b16 {%0,%1}, [%2];"
                 : "=r"(r[0]), "=r"(r[1]) : "r"(addr));
}
__device__ __forceinline__ void ldsm2t(u32* r, u32 addr) {
    asm volatile("ldmatrix.sync.aligned.m8n8.x2.trans.shared.b16 {%0,%1}, [%2];"
                 : "=r"(r[0]), "=r"(r[1]) : "r"(addr));
}

__device__ __forceinline__ void mma_bf16(float* c, const u32* a, u32 b0, u32 b1) {
    asm volatile(
        "mma.sync.aligned.m16n8k16.row.col.f32.bf16.bf16.f32 "
        "{%0,%1,%2,%3}, {%4,%5,%6,%7}, {%8,%9}, {%0,%1,%2,%3};"
        : "+f"(c[0]), "+f"(c[1]), "+f"(c[2]), "+f"(c[3])
        : "r"(a[0]), "r"(a[1]), "r"(a[2]), "r"(a[3]), "r"(b0), "r"(b1));
}

// pack high-16-bits of two fp32 -> bf16x2 (truncation) in one PRMT
__device__ __forceinline__ u32 prmt_hi16(u32 a, u32 b) {
    u32 r;
    asm("prmt.b32 %0, %1, %2, 0x7632;" : "=r"(r) : "r"(a), "r"(b));
    return r;
}

// truncation split: hi = trunc16(x), lo = trunc16(x - hi). ~6 instr / 2 floats.
__device__ __forceinline__ void split2(float f0, float f1, u32& hi, u32& lo) {
    u32 u0 = __float_as_uint(f0), u1 = __float_as_uint(f1);
    hi = prmt_hi16(u0, u1);
    float h0 = __uint_as_float(u0 & 0xFFFF0000u);
    float h1 = __uint_as_float(u1 & 0xFFFF0000u);
    float l0 = f0 - h0, l1 = f1 - h1;
    lo = prmt_hi16(__float_as_uint(l0), __float_as_uint(l1));
}

// ================= Kernel A: HMMA kv partial, cp.async pipelined (round-12/13 body) =================
#define KV_KF32 0                       // 2 x 8192
#define KV_VF32 16384                   // 2 x 8192
#define KV_KHI  32768                   // 32*144 = 4608 each
#define KV_KLO  (32768 + 4608)
#define KV_VHI  (32768 + 9216)
#define KV_VLO  (32768 + 13824)
#define KV_SMEM_BYTES (32768 + 18432)   // 51200

__global__ __launch_bounds__(128) void kv_mma_kernel(
    const float* __restrict__ kin, const float* __restrict__ vin,
    const float* __restrict__ kv_mask)
{
    extern __shared__ char smem[];
    const u32 sb = smem_u32(smem);
    const u32 sb_khi = sb + KV_KHI, sb_klo = sb + KV_KLO;
    const u32 sb_vhi = sb + KV_VHI, sb_vlo = sb + KV_VLO;

    const int nh = blockIdx.x;
    const int n = nh >> 3, h = nh & 7;
    const int s0 = blockIdx.y * 256;
    const int t = threadIdx.x;
    const int lane = t & 31, w = t >> 5;

    if (t < 32) {
        *(uint4*)(smem + KV_VHI + t * BSTR + 128) = make_uint4(0x3F80u, 0u, 0u, 0u);
        *(uint4*)(smem + KV_VLO + t * BSTR + 128) = make_uint4(0u, 0u, 0u, 0u);
    }

    const size_t gbase = (((size_t)n * SSZ + s0) * HH + h) * DD;

    #pragma unroll
    for (int j = 0; j < 4; j++) {
        int c = t + j * 128;
        int r = c >> 4, c16 = c & 15;
        size_t g = gbase + (size_t)r * HH * DD + c16 * 4;
        cpasync16(sb + KV_KF32 + c * 16, kin + g);
        cpasync16(sb + KV_VF32 + c * 16, vin + g);
    }
    CP_COMMIT();

    float acc[9][4] = {};

    #pragma unroll 1
    for (int tile = 0; tile < 8; tile++) {
        const int buf = tile & 1;
        if (tile < 7) {
            const int nb = buf ^ 1;
            #pragma unroll
            for (int j = 0; j < 4; j++) {
                int c = t + j * 128;
                int r = c >> 4, c16 = c & 15;
                size_t g = gbase + (size_t)((tile + 1) * 32 + r) * HH * DD + c16 * 4;
                cpasync16(sb + KV_KF32 + nb * 8192 + c * 16, kin + g);
                cpasync16(sb + KV_VF32 + nb * 8192 + c * 16, vin + g);
            }
            CP_COMMIT();
            CP_WAIT1();
        } else {
            CP_WAIT0();
        }

        #pragma unroll
        for (int e = 0; e < 4; e++) {
            int idx = t + e * 128;
            int r = idx >> 4, c4 = (idx & 15) * 4;
            int s = s0 + tile * 32 + r;
            float m = kv_mask[n * SSZ + s];
            float4 kq = *(const float4*)(smem + KV_KF32 + buf * 8192 + idx * 16);
            float4 vq = *(const float4*)(smem + KV_VF32 + buf * 8192 + idx * 16);
            u32 kh0, kl0, kh1, kl1, vh0, vl0, vh1, vl1;
            split2(fmap(kq.x) * m, fmap(kq.y) * m, kh0, kl0);
            split2(fmap(kq.z) * m, fmap(kq.w) * m, kh1, kl1);
            split2(vq.x * m, vq.y * m, vh0, vl0);
            split2(vq.z * m, vq.w * m, vh1, vl1);
            u32 off = r * BSTR + c4 * 2;
            *(u32*)(smem + KV_KHI + off) = kh0; *(u32*)(smem + KV_KHI + off + 4) = kh1;
            *(u32*)(smem + KV_KLO + off) = kl0; *(u32*)(smem + KV_KLO + off + 4) = kl1;
            *(u32*)(smem + KV_VHI + off) = vh0; *(u32*)(smem + KV_VHI + off + 4) = vh1;
            *(u32*)(smem + KV_VLO + off) = vl0; *(u32*)(smem + KV_VLO + off + 4) = vl1;
        }
        __syncthreads();

        #pragma unroll
        for (int kk = 0; kk < 2; kk++) {
            u32 arow = (u32)((lane & 7) + ((lane >> 4) & 1) * 8 + kk * 16);
            u32 acol = (u32)(w * 16 + ((lane >> 3) & 1) * 8);
            u32 aoff = arow * BSTR + acol * 2;
            u32 ahi[4], alo[4];
            ldsm4t(ahi, sb_khi + aoff);
            ldsm4t(alo, sb_klo + aoff);

            u32 brow = (u32)((lane & 7) + ((lane >> 3) & 1) * 8 + kk * 16);
            #pragma unroll
            for (int p = 0; p < 4; p++) {
                u32 boff = brow * BSTR + (u32)(p * 16 + ((lane >> 4) & 1) * 8) * 2;
                u32 bh[4], bl[4];
                ldsm4t(bh, sb_vhi + boff);
                ldsm4t(bl, sb_vlo + boff);
                mma_bf16(acc[2 * p],     ahi, bh[0], bh[1]);
                mma_bf16(acc[2 * p],     ahi, bl[0], bl[1]);
                mma_bf16(acc[2 * p],     alo, bh[0], bh[1]);
                mma_bf16(acc[2 * p + 1], ahi, bh[2], bh[3]);
                mma_bf16(acc[2 * p + 1], ahi, bl[2], bl[3]);
                mma_bf16(acc[2 * p + 1], alo, bh[2], bh[3]);
            }
            {
                u32 b2off = brow * BSTR + 64 * 2;
                u32 bh[2], bl[2];
                ldsm2t(bh, sb_vhi + b2off);
                ldsm2t(bl, sb_vlo + b2off);
                mma_bf16(acc[8], ahi, bh[0], bh[1]);
                mma_bf16(acc[8], ahi, bl[0], bl[1]);
                mma_bf16(acc[8], alo, bh[0], bh[1]);
            }
        }
        __syncthreads();
    }

    float* part = &g_part[(nh * CHA + blockIdx.y) * PART_STRIDE];
    const int r0 = w * 16 + (lane >> 2);
    const int col = 2 * (lane & 3);
    #pragma unroll
    for (int nt = 0; nt < 8; nt++) {
        *(float2*)&part[r0 * 64 + nt * 8 + col] = make_float2(acc[nt][0], acc[nt][1]);
        *(float2*)&part[(r0 + 8) * 64 + nt * 8 + col] = make_float2(acc[nt][2], acc[nt][3]);
    }
    if ((lane & 3) == 0) {
        part[4096 + r0] = acc[8][0];
        part[4096 + r0 + 8] = acc[8][2];
    }
}

// ================= Reduce: fp32 sum -> transposed bf16 hi/lo (truncation split) =================
__global__ __launch_bounds__(256) void kv_reduce_kernel() {
    int idx = blockIdx.x * 256 + threadIdx.x;
    int nh = idx / PART_STRIDE;
    int el = idx - nh * PART_STRIDE;
    float s = 0.f;
    #pragma unroll 8
    for (int ch = 0; ch < CHA; ch++)
        s += g_part[(nh * CHA + ch) * PART_STRIDE + el];

    u32 ub = __float_as_uint(s);
    unsigned short hib = (unsigned short)(ub >> 16);
    float hf = __uint_as_float(ub & 0xFFFF0000u);
    float lf = s - hf;
    unsigned short lob = (unsigned short)(__float_as_uint(lf) >> 16);

    int dst;
    if (el < 4096) {
        int d = el >> 6, v = el & 63;
        dst = nh * (BR * DD) + v * 64 + d;
    } else {
        int d = el - 4096;
        dst = nh * (BR * DD) + 64 * 64 + d;
    }
    *(unsigned short*)&g_kvbf_hi[dst] = hib;
    *(unsigned short*)&g_kvbf_lo[dst] = lob;
}

// ================= Kernel B: HMMA out (round-10 verified body) =================
#define SM_AHI 0
#define SM_ALO (128 * BSTR)
#define SM_BHI (2 * 128 * BSTR)
#define SM_BLO (SM_BHI + BR * BSTR)
#define OUT_SMEM_BYTES (SM_BLO + BR * BSTR)   // 57600

__global__ __launch_bounds__(256) void out_mma_kernel(
    const float* __restrict__ qin, const float* __restrict__ q_mask,
    float* __restrict__ out)
{
    extern __shared__ char smem[];
    const u32 sb = smem_u32(smem);

    const int nh = blockIdx.x;
    const int n = nh >> 3, h = nh & 7;
    const int l0 = blockIdx.y * 128;
    const int t = threadIdx.x;
    const int lane = t & 31, w = t >> 5;

    {
        const u32* ghi = (const u32*)&g_kvbf_hi[nh * (BR * DD)];
        const u32* glo = (const u32*)&g_kvbf_lo[nh * (BR * DD)];
        #pragma unroll
        for (int e = 0; e < 9; e++) {
            int idx = t + e * 256;
            int row = idx >> 5, c = idx & 31;
            *(u32*)(smem + SM_BHI + row * BSTR + c * 4) = ghi[idx];
            *(u32*)(smem + SM_BLO + row * BSTR + c * 4) = glo[idx];
        }
    }

    #pragma unroll
    for (int e = 0; e < 8; e++) {
        int idx = t + e * 256;
        int l = idx >> 4, c4 = (idx & 15) * 4;
        float m = q_mask[n * LL + l0 + l];
        size_t g = (((size_t)(n * LL + l0 + l)) * HH + h) * DD + c4;
        float4 x = *(const float4*)&qin[g];
        u32 h0, lo0, h1, lo1;
        split2(fmap(x.x) * m, fmap(x.y) * m, h0, lo0);
        split2(fmap(x.z) * m, fmap(x.w) * m, h1, lo1);
        u32 off = l * BSTR + c4 * 2;
        *(u32*)(smem + SM_AHI + off)     = h0;
        *(u32*)(smem + SM_AHI + off + 4) = h1;
        *(u32*)(smem + SM_ALO + off)     = lo0;
        *(u32*)(smem + SM_ALO + off + 4) = lo1;
    }
    __syncthreads();

    const int mbase = w * 16;
    float acc[9][4] = {};

    const u32 a_off = (u32)(mbase + (lane & 15)) * BSTR + (u32)(lane >> 4) * 16;
    const int bi = lane & 7, bg = lane >> 3;
    const u32 b4_off = (u32)(bi + ((bg & 2) << 2)) * BSTR + (u32)(bg & 1) * 16;
    const u32 b2_off = (u32)(64 + bi) * BSTR + (u32)(bg & 1) * 16;

    #pragma unroll
    for (int kk = 0; kk < 4; kk++) {
        const u32 koff = kk * 32;
        u32 ahi[4], alo[4];
        ldsm4(ahi, sb + SM_AHI + a_off + koff);
        ldsm4(alo, sb + SM_ALO + a_off + koff);

        #pragma unroll
        for (int p = 0; p < 4; p++) {
            u32 bh[4], bl[4];
            u32 ba = (u32)(p * 16) * BSTR + b4_off + koff;
            ldsm4(bh, sb + SM_BHI + ba);
            ldsm4(bl, sb + SM_BLO + ba);
            mma_bf16(acc[2 * p],     ahi, bh[0], bh[1]);
            mma_bf16(acc[2 * p],     ahi, bl[0], bl[1]);
            mma_bf16(acc[2 * p],     alo, bh[0], bh[1]);
            mma_bf16(acc[2 * p + 1], ahi, bh[2], bh[3]);
            mma_bf16(acc[2 * p + 1], ahi, bl[2], bl[3]);
            mma_bf16(acc[2 * p + 1], alo, bh[2], bh[3]);
        }
        {
            u32 bh[2], bl[2];
            ldsm2(bh, sb + SM_BHI + b2_off + koff);
            ldsm2(bl, sb + SM_BLO + b2_off + koff);
            mma_bf16(acc[8], ahi, bh[0], bh[1]);
            mma_bf16(acc[8], ahi, bl[0], bl[1]);
            mma_bf16(acc[8], alo, bh[0], bh[1]);
        }
    }

    float n0 = __shfl_sync(0xffffffffu, acc[8][0], lane & ~3);
    float n1 = __shfl_sync(0xffffffffu, acc[8][2], lane & ~3);
    float dv0 = 1.f / (n0 + EPS);
    float dv1 = 1.f / (n1 + EPS);

    const int r0 = l0 + mbase + (lane >> 2);
    const int col = 2 * (lane & 3);
    size_t g0 = (((size_t)(n * LL + r0)) * HH + h) * DD;
    size_t g1 = g0 + (size_t)8 * HH * DD;

    #pragma unroll
    for (int nt = 0; nt < 8; nt++) {
        *(float2*)&out[g0 + nt * 8 + col] =
            make_float2(acc[nt][0] * dv0, acc[nt][1] * dv0);
        *(float2*)&out[g1 + nt * 8 + col] =
            make_float2(acc[nt][2] * dv1, acc[nt][3] * dv1);
    }
}

extern "C" void kernel_launch(void* const* d_in, const int* in_sizes, int n_in,
                              void* d_out, int out_size)
{
    const float* q   = (const float*)d_in[0];
    const float* k   = (const float*)d_in[1];
    const float* v   = (const float*)d_in[2];
    const float* qm  = (const float*)d_in[3];
    const float* kvm = (const float*)d_in[4];
    float* out = (float*)d_out;

    static bool attr_done = false;
    if (!attr_done) {
        cudaFuncSetAttribute(kv_mma_kernel,
                             cudaFuncAttributeMaxDynamicSharedMemorySize,
                             KV_SMEM_BYTES);
        cudaFuncSetAttribute(out_mma_kernel,
                             cudaFuncAttributeMaxDynamicSharedMemorySize,
                             OUT_SMEM_BYTES);
        attr_done = true;
    }

    kv_mma_kernel<<<dim3(NH, CHA), 128, KV_SMEM_BYTES>>>(k, v, kvm);
    kv_reduce_kernel<<<(NH * PART_STRIDE) / 256, 256>>>();
    out_mma_kernel<<<dim3(NH, 64), 256, OUT_SMEM_BYTES>>>(q, qm, out);
}

// round 16
// speedup vs baseline: 1.1501x; 1.0669x over previous
#include <cuda_runtime.h>
#include <cuda_bf16.h>
#include <cstdint>

#define NB 4
#define LL 8192
#define SSZ 8192
#define HH 8
#define DD 64
#define NH (NB * HH)
#define CHA 16           // s-chunks per (n,h); 512 s per chunk -> single wave
#define PART_STRIDE 4160 // 4096 kv + 64 ksum
#define EPS 1e-6f
#define BR 72            // B rows: 64 kv^T + 1 ksum + 7 zero
#define BSTR 144         // bf16 row stride bytes

typedef unsigned long long u64;
typedef unsigned int u32;

__device__ float g_part[NH * CHA * PART_STRIDE];
__device__ __nv_bfloat16 g_kvbf_hi[NH * BR * DD];
__device__ __nv_bfloat16 g_kvbf_lo[NH * BR * DD];

__device__ __forceinline__ float fmap(float x) {
    return x > 0.f ? x + 1.f : __expf(x);
}

__device__ __forceinline__ u32 smem_u32(const void* p) {
    u32 a;
    asm("{ .reg .u64 t; cvta.to.shared.u64 t, %1; cvt.u32.u64 %0, t; }"
        : "=r"(a) : "l"(p));
    return a;
}

__device__ __forceinline__ void cpasync16(u32 saddr, const void* gptr) {
    asm volatile("cp.async.cg.shared.global [%0], [%1], 16;"
                 :: "r"(saddr), "l"(gptr));
}
#define CP_COMMIT() asm volatile("cp.async.commit_group;" ::: "memory")
#define CP_WAIT1()  asm volatile("cp.async.wait_group 1;" ::: "memory")
#define CP_WAIT0()  asm volatile("cp.async.wait_group 0;" ::: "memory")

__device__ __forceinline__ void ldsm4(u32* r, u32 addr) {
    asm volatile("ldmatrix.sync.aligned.m8n8.x4.shared.b16 {%0,%1,%2,%3}, [%4];"
                 : "=r"(r[0]), "=r"(r[1]), "=r"(r[2]), "=r"(r[3]) : "r"(addr));
}
__device__ __forceinline__ void ldsm4t(u32* r, u32 addr) {
    asm volatile("ldmatrix.sync.aligned.m8n8.x4.trans.shared.b16 {%0,%1,%2,%3}, [%4];"
                 : "=r"(r[0]), "=r"(r[1]), "=r"(r[2]), "=r"(r[3]) : "r"(addr));
}
__device__ __forceinline__ void ldsm2(u32* r, u32 addr) {
    asm volatile("ldmatrix.sync.aligned.m8n8.x2.shared.b16 {%0,%1}, [%2];"
                 : "=r"(r[0]), "=r"(r[1]) : "r"(addr));
}
__device__ __forceinline__ void ldsm2t(u32* r, u32 addr) {
    asm volatile("ldmatrix.sync.aligned.m8n8.x2.trans.shared.b16 {%0,%1}, [%2];"
                 : "=r"(r[0]), "=r"(r[1]) : "r"(addr));
}

__device__ __forceinline__ void mma_bf16(float* c, const u32* a, u32 b0, u32 b1) {
    asm volatile(
        "mma.sync.aligned.m16n8k16.row.col.f32.bf16.bf16.f32 "
        "{%0,%1,%2,%3}, {%4,%5,%6,%7}, {%8,%9}, {%0,%1,%2,%3};"
        : "+f"(c[0]), "+f"(c[1]), "+f"(c[2]), "+f"(c[3])
        : "r"(a[0]), "r"(a[1]), "r"(a[2]), "r"(a[3]), "r"(b0), "r"(b1));
}

// pack high-16-bits of two fp32 -> bf16x2 (truncation) in one PRMT
__device__ __forceinline__ u32 prmt_hi16(u32 a, u32 b) {
    u32 r;
    asm("prmt.b32 %0, %1, %2, 0x7632;" : "=r"(r) : "r"(a), "r"(b));
    return r;
}

// truncation split: hi = trunc16(x), lo = trunc16(x - hi)
__device__ __forceinline__ void split2(float f0, float f1, u32& hi, u32& lo) {
    u32 u0 = __float_as_uint(f0), u1 = __float_as_uint(f1);
    hi = prmt_hi16(u0, u1);
    float h0 = __uint_as_float(u0 & 0xFFFF0000u);
    float h1 = __uint_as_float(u1 & 0xFFFF0000u);
    float l0 = f0 - h0, l1 = f1 - h1;
    lo = prmt_hi16(__float_as_uint(l0), __float_as_uint(l1));
}

// ================= Kernel A: HMMA kv partial, cp.async pipelined =================
#define KV_KF32 0                       // 2 x 8192
#define KV_VF32 16384                   // 2 x 8192
#define KV_KHI  32768                   // 32*144 = 4608 each
#define KV_KLO  (32768 + 4608)
#define KV_VHI  (32768 + 9216)
#define KV_VLO  (32768 + 13824)
#define KV_SMEM_BYTES (32768 + 18432)   // 51200

__global__ __launch_bounds__(128) void kv_mma_kernel(
    const float* __restrict__ kin, const float* __restrict__ vin,
    const float* __restrict__ kv_mask)
{
    extern __shared__ char smem[];
    const u32 sb = smem_u32(smem);
    const u32 sb_khi = sb + KV_KHI, sb_klo = sb + KV_KLO;
    const u32 sb_vhi = sb + KV_VHI, sb_vlo = sb + KV_VLO;

    const int nh = blockIdx.x;
    const int n = nh >> 3, h = nh & 7;
    const int s0 = blockIdx.y * 512;
    const int t = threadIdx.x;
    const int lane = t & 31, w = t >> 5;

    if (t < 32) {
        *(uint4*)(smem + KV_VHI + t * BSTR + 128) = make_uint4(0x3F80u, 0u, 0u, 0u);
        *(uint4*)(smem + KV_VLO + t * BSTR + 128) = make_uint4(0u, 0u, 0u, 0u);
    }

    const size_t gbase = (((size_t)n * SSZ + s0) * HH + h) * DD;

    #pragma unroll
    for (int j = 0; j < 4; j++) {
        int c = t + j * 128;
        int r = c >> 4, c16 = c & 15;
        size_t g = gbase + (size_t)r * HH * DD + c16 * 4;
        cpasync16(sb + KV_KF32 + c * 16, kin + g);
        cpasync16(sb + KV_VF32 + c * 16, vin + g);
    }
    CP_COMMIT();

    float acc[9][4] = {};

    #pragma unroll 1
    for (int tile = 0; tile < 16; tile++) {
        const int buf = tile & 1;
        if (tile < 15) {
            const int nb = buf ^ 1;
            #pragma unroll
            for (int j = 0; j < 4; j++) {
                int c = t + j * 128;
                int r = c >> 4, c16 = c & 15;
                size_t g = gbase + (size_t)((tile + 1) * 32 + r) * HH * DD + c16 * 4;
                cpasync16(sb + KV_KF32 + nb * 8192 + c * 16, kin + g);
                cpasync16(sb + KV_VF32 + nb * 8192 + c * 16, vin + g);
            }
            CP_COMMIT();
            CP_WAIT1();
        } else {
            CP_WAIT0();
        }

        #pragma unroll
        for (int e = 0; e < 4; e++) {
            int idx = t + e * 128;
            int r = idx >> 4, c4 = (idx & 15) * 4;
            int s = s0 + tile * 32 + r;
            float m = kv_mask[n * SSZ + s];
            float4 kq = *(const float4*)(smem + KV_KF32 + buf * 8192 + idx * 16);
            float4 vq = *(const float4*)(smem + KV_VF32 + buf * 8192 + idx * 16);
            u32 kh0, kl0, kh1, kl1, vh0, vl0, vh1, vl1;
            split2(fmap(kq.x) * m, fmap(kq.y) * m, kh0, kl0);
            split2(fmap(kq.z) * m, fmap(kq.w) * m, kh1, kl1);
            split2(vq.x * m, vq.y * m, vh0, vl0);
            split2(vq.z * m, vq.w * m, vh1, vl1);
            u32 off = r * BSTR + c4 * 2;
            *(u32*)(smem + KV_KHI + off) = kh0; *(u32*)(smem + KV_KHI + off + 4) = kh1;
            *(u32*)(smem + KV_KLO + off) = kl0; *(u32*)(smem + KV_KLO + off + 4) = kl1;
            *(u32*)(smem + KV_VHI + off) = vh0; *(u32*)(smem + KV_VHI + off + 4) = vh1;
            *(u32*)(smem + KV_VLO + off) = vl0; *(u32*)(smem + KV_VLO + off + 4) = vl1;
        }
        __syncthreads();

        #pragma unroll
        for (int kk = 0; kk < 2; kk++) {
            u32 arow = (u32)((lane & 7) + ((lane >> 4) & 1) * 8 + kk * 16);
            u32 acol = (u32)(w * 16 + ((lane >> 3) & 1) * 8);
            u32 aoff = arow * BSTR + acol * 2;
            u32 ahi[4], alo[4];
            ldsm4t(ahi, sb_khi + aoff);
            ldsm4t(alo, sb_klo + aoff);

            u32 brow = (u32)((lane & 7) + ((lane >> 3) & 1) * 8 + kk * 16);
            #pragma unroll
            for (int p = 0; p < 4; p++) {
                u32 boff = brow * BSTR + (u32)(p * 16 + ((lane >> 4) & 1) * 8) * 2;
                u32 bh[4], bl[4];
                ldsm4t(bh, sb_vhi + boff);
                ldsm4t(bl, sb_vlo + boff);
                mma_bf16(acc[2 * p],     ahi, bh[0], bh[1]);
                mma_bf16(acc[2 * p],     ahi, bl[0], bl[1]);
                mma_bf16(acc[2 * p],     alo, bh[0], bh[1]);
                mma_bf16(acc[2 * p + 1], ahi, bh[2], bh[3]);
                mma_bf16(acc[2 * p + 1], ahi, bl[2], bl[3]);
                mma_bf16(acc[2 * p + 1], alo, bh[2], bh[3]);
            }
            {
                u32 b2off = brow * BSTR + 64 * 2;
                u32 bh[2], bl[2];
                ldsm2t(bh, sb_vhi + b2off);
                ldsm2t(bl, sb_vlo + b2off);
                mma_bf16(acc[8], ahi, bh[0], bh[1]);
                mma_bf16(acc[8], ahi, bl[0], bl[1]);
                mma_bf16(acc[8], alo, bh[0], bh[1]);
            }
        }
        __syncthreads();
    }

    float* part = &g_part[(nh * CHA + blockIdx.y) * PART_STRIDE];
    const int r0 = w * 16 + (lane >> 2);
    const int col = 2 * (lane & 3);
    #pragma unroll
    for (int nt = 0; nt < 8; nt++) {
        *(float2*)&part[r0 * 64 + nt * 8 + col] = make_float2(acc[nt][0], acc[nt][1]);
        *(float2*)&part[(r0 + 8) * 64 + nt * 8 + col] = make_float2(acc[nt][2], acc[nt][3]);
    }
    if ((lane & 3) == 0) {
        part[4096 + r0] = acc[8][0];
        part[4096 + r0 + 8] = acc[8][2];
    }
}

// ================= Reduce: fp32 sum -> transposed bf16 hi/lo =================
__global__ __launch_bounds__(256) void kv_reduce_kernel() {
    int idx = blockIdx.x * 256 + threadIdx.x;
    int nh = idx / PART_STRIDE;
    int el = idx - nh * PART_STRIDE;
    float s = 0.f;
    #pragma unroll 8
    for (int ch = 0; ch < CHA; ch++)
        s += g_part[(nh * CHA + ch) * PART_STRIDE + el];

    u32 ub = __float_as_uint(s);
    unsigned short hib = (unsigned short)(ub >> 16);
    float hf = __uint_as_float(ub & 0xFFFF0000u);
    float lf = s - hf;
    unsigned short lob = (unsigned short)(__float_as_uint(lf) >> 16);

    int dst;
    if (el < 4096) {
        int d = el >> 6, v = el & 63;
        dst = nh * (BR * DD) + v * 64 + d;
    } else {
        int d = el - 4096;
        dst = nh * (BR * DD) + 64 * 64 + d;
    }
    *(unsigned short*)&g_kvbf_hi[dst] = hib;
    *(unsigned short*)&g_kvbf_lo[dst] = lob;
}

// ================= Kernel B: HMMA out (verified body, reg-capped for 3 CTAs/SM) =================
#define SM_AHI 0
#define SM_ALO (128 * BSTR)
#define SM_BHI (2 * 128 * BSTR)
#define SM_BLO (SM_BHI + BR * BSTR)
#define OUT_SMEM_BYTES (SM_BLO + BR * BSTR)   // 57600

__global__ __launch_bounds__(256, 3) void out_mma_kernel(
    const float* __restrict__ qin, const float* __restrict__ q_mask,
    float* __restrict__ out)
{
    extern __shared__ char smem[];
    const u32 sb = smem_u32(smem);

    const int nh = blockIdx.x;
    const int n = nh >> 3, h = nh & 7;
    const int l0 = blockIdx.y * 128;
    const int t = threadIdx.x;
    const int lane = t & 31, w = t >> 5;

    {
        const u32* ghi = (const u32*)&g_kvbf_hi[nh * (BR * DD)];
        const u32* glo = (const u32*)&g_kvbf_lo[nh * (BR * DD)];
        #pragma unroll
        for (int e = 0; e < 9; e++) {
            int idx = t + e * 256;
            int row = idx >> 5, c = idx & 31;
            *(u32*)(smem + SM_BHI + row * BSTR + c * 4) = ghi[idx];
            *(u32*)(smem + SM_BLO + row * BSTR + c * 4) = glo[idx];
        }
    }

    #pragma unroll
    for (int e = 0; e < 8; e++) {
        int idx = t + e * 256;
        int l = idx >> 4, c4 = (idx & 15) * 4;
        float m = q_mask[n * LL + l0 + l];
        size_t g = (((size_t)(n * LL + l0 + l)) * HH + h) * DD + c4;
        float4 x = *(const float4*)&qin[g];
        u32 h0, lo0, h1, lo1;
        split2(fmap(x.x) * m, fmap(x.y) * m, h0, lo0);
        split2(fmap(x.z) * m, fmap(x.w) * m, h1, lo1);
        u32 off = l * BSTR + c4 * 2;
        *(u32*)(smem + SM_AHI + off)     = h0;
        *(u32*)(smem + SM_AHI + off + 4) = h1;
        *(u32*)(smem + SM_ALO + off)     = lo0;
        *(u32*)(smem + SM_ALO + off + 4) = lo1;
    }
    __syncthreads();

    const int mbase = w * 16;
    float acc[9][4] = {};

    const u32 a_off = (u32)(mbase + (lane & 15)) * BSTR + (u32)(lane >> 4) * 16;
    const int bi = lane & 7, bg = lane >> 3;
    const u32 b4_off = (u32)(bi + ((bg & 2) << 2)) * BSTR + (u32)(bg & 1) * 16;
    const u32 b2_off = (u32)(64 + bi) * BSTR + (u32)(bg & 1) * 16;

    #pragma unroll
    for (int kk = 0; kk < 4; kk++) {
        const u32 koff = kk * 32;
        u32 ahi[4], alo[4];
        ldsm4(ahi, sb + SM_AHI + a_off + koff);
        ldsm4(alo, sb + SM_ALO + a_off + koff);

        #pragma unroll
        for (int p = 0; p < 4; p++) {
            u32 bh[4], bl[4];
            u32 ba = (u32)(p * 16) * BSTR + b4_off + koff;
            ldsm4(bh, sb + SM_BHI + ba);
            ldsm4(bl, sb + SM_BLO + ba);
            mma_bf16(acc[2 * p],     ahi, bh[0], bh[1]);
            mma_bf16(acc[2 * p],     ahi, bl[0], bl[1]);
            mma_bf16(acc[2 * p],     alo, bh[0], bh[1]);
            mma_bf16(acc[2 * p + 1], ahi, bh[2], bh[3]);
            mma_bf16(acc[2 * p + 1], ahi, bl[2], bl[3]);
            mma_bf16(acc[2 * p + 1], alo, bh[2], bh[3]);
        }
        {
            u32 bh[2], bl[2];
            ldsm2(bh, sb + SM_BHI + b2_off + koff);
            ldsm2(bl, sb + SM_BLO + b2_off + koff);
            mma_bf16(acc[8], ahi, bh[0], bh[1]);
            mma_bf16(acc[8], ahi, bl[0], bl[1]);
            mma_bf16(acc[8], alo, bh[0], bh[1]);
        }
    }

    float n0 = __shfl_sync(0xffffffffu, acc[8][0], lane & ~3);
    float n1 = __shfl_sync(0xffffffffu, acc[8][2], lane & ~3);
    float dv0 = 1.f / (n0 + EPS);
    float dv1 = 1.f / (n1 + EPS);

    const int r0 = l0 + mbase + (lane >> 2);
    const int col = 2 * (lane & 3);
    size_t g0 = (((size_t)(n * LL + r0)) * HH + h) * DD;
    size_t g1 = g0 + (size_t)8 * HH * DD;

    #pragma unroll
    for (int nt = 0; nt < 8; nt++) {
        *(float2*)&out[g0 + nt * 8 + col] =
            make_float2(acc[nt][0] * dv0, acc[nt][1] * dv0);
        *(float2*)&out[g1 + nt * 8 + col] =
            make_float2(acc[nt][2] * dv1, acc[nt][3] * dv1);
    }
}

extern "C" void kernel_launch(void* const* d_in, const int* in_sizes, int n_in,
                              void* d_out, int out_size)
{
    const float* q   = (const float*)d_in[0];
    const float* k   = (const float*)d_in[1];
    const float* v   = (const float*)d_in[2];
    const float* qm  = (const float*)d_in[3];
    const float* kvm = (const float*)d_in[4];
    float* out = (float*)d_out;

    static bool attr_done = false;
    if (!attr_done) {
        cudaFuncSetAttribute(kv_mma_kernel,
                             cudaFuncAttributeMaxDynamicSharedMemorySize,
                             KV_SMEM_BYTES);
        cudaFuncSetAttribute(out_mma_kernel,
                             cudaFuncAttributeMaxDynamicSharedMemorySize,
                             OUT_SMEM_BYTES);
        attr_done = true;
    }

    kv_mma_kernel<<<dim3(NH, CHA), 128, KV_SMEM_BYTES>>>(k, v, kvm);
    kv_reduce_kernel<<<(NH * PART_STRIDE) / 256, 256>>>();
    out_mma_kernel<<<dim3(NH, 64), 256, OUT_SMEM_BYTES>>>(q, qm, out);
}